// round 1
// baseline (speedup 1.0000x reference)
#include <cuda_runtime.h>
#include <cfloat>
#include <cstdint>

#define Bn  8
#define Ls  3136      // 56*56
#define Cn  64
#define HID 32
#define KN  30
#define NV  (Bn*Ls)   // 25088 global vertices/edges

// ---------------- device scratch (static globals; no allocations) ----------------
__device__ float g_sq  [NV];
__device__ float g_d2  [(size_t)Bn*Ls*Ls];      // 314.7 MB distance matrices
__device__ int   g_nbr [(size_t)NV*KN];         // per-edge neighbor lists (sample-local idx)
__device__ int   g_dvi [NV];                    // vertex in-degree (counts)
__device__ int   g_off [NV];                    // CSR offsets (exclusive scan of g_dvi)
__device__ int   g_cnt [NV];                    // CSR fill cursors
__device__ int   g_adj [(size_t)NV*KN];         // CSR: edges incident to each vertex
__device__ float g_h1  [(size_t)NV*HID];        // conv1 theta+bn
__device__ float g_y1  [(size_t)NV*HID];        // conv1 v2e means
__device__ float g_o1  [(size_t)NV*HID];        // conv1 output (after e2v + relu)
__device__ float g_h2  [(size_t)NV*Cn];         // conv2 theta+bn
__device__ float g_y2  [(size_t)NV*Cn];         // conv2 v2e means

// 1/sqrt(1 + 1e-5) computed in double, rounded to f32 (matches reference)
#define BN_SCALE 0.99999500003749969f

// ---------------- kernel 0: zero counters ----------------
__global__ void zero_kernel() {
    int t = blockIdx.x * blockDim.x + threadIdx.x;
    if (t < NV) { g_cnt[t] = 0; g_dvi[t] = 0; }
}

// ---------------- kernel 1: row squared norms (warp per vertex) ----------------
__global__ void sq_kernel(const float* __restrict__ x) {
    int gv = blockIdx.x * 8 + (threadIdx.x >> 5);
    int lane = threadIdx.x & 31;
    const float* p = x + (size_t)gv * Cn;
    float a = p[lane] * p[lane] + p[lane + 32] * p[lane + 32];
    #pragma unroll
    for (int off = 16; off; off >>= 1) a += __shfl_down_sync(0xffffffffu, a, off);
    if (lane == 0) g_sq[gv] = a;
}

// ---------------- kernel 2: d2 = sq_i + sq_j - 2*(ft @ ft^T), 64x64 tiles ----------------
__global__ void __launch_bounds__(64) dist_kernel(const float* __restrict__ x) {
    int s = blockIdx.z;
    const float* A  = x + (size_t)s * Ls * Cn;
    float*       D  = g_d2 + (size_t)s * Ls * Ls;
    const float* sq = g_sq + s * Ls;
    int i0 = blockIdx.y << 6, j0 = blockIdx.x << 6;

    __shared__ __align__(16) float Ast[64][68];  // [k][m], 68 keeps rows 16B-aligned
    __shared__ __align__(16) float Bst[64][68];  // [k][n]
    int tid = threadIdx.x;   // 64 threads

    // load both 64x64 tiles (transposed into [k][row])
    for (int f = tid; f < 1024; f += 64) {
        int m = f >> 4, kq = (f & 15) << 2;
        float4 av = *(const float4*)(A + (size_t)(i0 + m) * Cn + kq);
        Ast[kq + 0][m] = av.x; Ast[kq + 1][m] = av.y; Ast[kq + 2][m] = av.z; Ast[kq + 3][m] = av.w;
        float4 bv = *(const float4*)(A + (size_t)(j0 + m) * Cn + kq);
        Bst[kq + 0][m] = bv.x; Bst[kq + 1][m] = bv.y; Bst[kq + 2][m] = bv.z; Bst[kq + 3][m] = bv.w;
    }
    __syncthreads();

    int m0 = (tid >> 3) << 3;  // 8x8 microtile
    int n0 = (tid & 7) << 3;
    float acc[8][8];
    #pragma unroll
    for (int r = 0; r < 8; r++)
        #pragma unroll
        for (int c = 0; c < 8; c++) acc[r][c] = 0.f;

    #pragma unroll 8
    for (int k = 0; k < 64; k++) {
        float a[8], b[8];
        *(float4*)(a)     = *(const float4*)&Ast[k][m0];
        *(float4*)(a + 4) = *(const float4*)&Ast[k][m0 + 4];
        *(float4*)(b)     = *(const float4*)&Bst[k][n0];
        *(float4*)(b + 4) = *(const float4*)&Bst[k][n0 + 4];
        #pragma unroll
        for (int r = 0; r < 8; r++)
            #pragma unroll
            for (int c = 0; c < 8; c++) acc[r][c] = fmaf(a[r], b[c], acc[r][c]);
    }

    float sqj[8];
    #pragma unroll
    for (int c = 0; c < 8; c++) sqj[c] = sq[j0 + n0 + c];
    #pragma unroll
    for (int r = 0; r < 8; r++) {
        float sqi = sq[i0 + m0 + r];
        float* drow = D + (size_t)(i0 + m0 + r) * Ls + j0 + n0;
        float4 o0 = make_float4(sqi + sqj[0] - 2.f * acc[r][0],
                                sqi + sqj[1] - 2.f * acc[r][1],
                                sqi + sqj[2] - 2.f * acc[r][2],
                                sqi + sqj[3] - 2.f * acc[r][3]);
        float4 o1 = make_float4(sqi + sqj[4] - 2.f * acc[r][4],
                                sqi + sqj[5] - 2.f * acc[r][5],
                                sqi + sqj[6] - 2.f * acc[r][6],
                                sqi + sqj[7] - 2.f * acc[r][7]);
        *(float4*)(drow)     = o0;
        *(float4*)(drow + 4) = o1;
    }
}

// ---------------- kernel 3: top-K smallest per row (tournament select) ----------------
__global__ void __launch_bounds__(128) topk_kernel() {
    int s = blockIdx.y, i = blockIdx.x;
    const float* row = g_d2 + ((size_t)s * Ls + i) * Ls;
    __shared__ float vals[Ls];
    __shared__ float wv[4];
    __shared__ int   wi[4];
    __shared__ int   s_win;
    __shared__ int   sel[KN];
    int tid = threadIdx.x;     // 128
    int lane = tid & 31, warp = tid >> 5;

    // each thread's stripe: t = tid, tid+128, ...; keep stripe min in registers
    float cv = FLT_MAX; int ci = -1;
    for (int t = tid; t < Ls; t += 128) {
        float v = row[t];
        vals[t] = v;
        if (v < cv) { cv = v; ci = t; }
    }
    __syncthreads();

    for (int it = 0; it < KN; it++) {
        float bv = cv; int bi = ci;
        #pragma unroll
        for (int off = 16; off; off >>= 1) {
            float ov = __shfl_down_sync(0xffffffffu, bv, off);
            int   oi = __shfl_down_sync(0xffffffffu, bi, off);
            if (ov < bv || (ov == bv && oi < bi)) { bv = ov; bi = oi; }
        }
        if (lane == 0) { wv[warp] = bv; wi[warp] = bi; }
        __syncthreads();
        if (tid == 0) {
            for (int w = 1; w < 4; w++)
                if (wv[w] < bv || (wv[w] == bv && wi[w] < bi)) { bv = wv[w]; bi = wi[w]; }
            sel[it] = bi;
            s_win = bi;
        }
        __syncthreads();
        int win = s_win;
        if ((win & 127) == tid) {           // owner: mark + rescan own stripe
            vals[win] = FLT_MAX;
            float nv = FLT_MAX; int ni = -1;
            for (int t = tid; t < Ls; t += 128) {
                float v = vals[t];
                if (v < nv) { nv = v; ni = t; }
            }
            cv = nv; ci = ni;
        }
        __syncthreads();
    }

    if (tid < KN) {
        int v = sel[tid];
        g_nbr[((size_t)s * Ls + i) * KN + tid] = v;
        atomicAdd(&g_dvi[s * Ls + v], 1);
    }
}

// ---------------- kernel 4: exclusive scan of degrees (single block) ----------------
__global__ void scan_kernel() {
    __shared__ int ps[1024];
    int tid = threadIdx.x;
    int start = tid * 25;                  // 1024*25 = 25600 >= 25088
    int sum = 0;
    for (int t = start; t < start + 25 && t < NV; t++) sum += g_dvi[t];
    ps[tid] = sum;
    __syncthreads();
    for (int off = 1; off < 1024; off <<= 1) {
        int v = (tid >= off) ? ps[tid - off] : 0;
        __syncthreads();
        ps[tid] += v;
        __syncthreads();
    }
    int excl = (tid == 0) ? 0 : ps[tid - 1];
    for (int t = start; t < start + 25 && t < NV; t++) {
        g_off[t] = excl;
        excl += g_dvi[t];
    }
}

// ---------------- kernel 5: CSR fill (warp per edge) ----------------
__global__ void fill_kernel() {
    int s = blockIdx.y;
    int e = blockIdx.x * 8 + (threadIdx.x >> 5);
    int lane = threadIdx.x & 31;
    int ge = s * Ls + e;
    if (lane < KN) {
        int v  = g_nbr[(size_t)ge * KN + lane];
        int gv = s * Ls + v;
        int pos = atomicAdd(&g_cnt[gv], 1);
        g_adj[g_off[gv] + pos] = ge;
    }
}

// ---------------- kernel 6: theta1 + BN (warp per vertex, 32 outputs) ----------------
__global__ void theta1_kernel(const float* __restrict__ x, const float* __restrict__ w1,
                              const float* __restrict__ b1, const float* __restrict__ g1,
                              const float* __restrict__ be1) {
    __shared__ float ws[Cn * HID];
    int tid = threadIdx.x;
    for (int t = tid; t < Cn * HID; t += 256) ws[t] = w1[t];
    __syncthreads();
    int gv = blockIdx.x * 8 + (tid >> 5);
    int lane = tid & 31;
    const float* f = x + (size_t)gv * Cn;
    float f0 = f[lane], f1 = f[lane + 32];
    float acc = 0.f;
    #pragma unroll
    for (int c = 0; c < 32; c++) acc = fmaf(__shfl_sync(0xffffffffu, f0, c), ws[c * HID + lane], acc);
    #pragma unroll
    for (int c = 0; c < 32; c++) acc = fmaf(__shfl_sync(0xffffffffu, f1, c), ws[(c + 32) * HID + lane], acc);
    g_h1[(size_t)gv * HID + lane] = (acc + b1[lane]) * (g1[lane] * BN_SCALE) + be1[lane];
}

// ---------------- kernel 7: v2e mean, conv1 (warp per edge, F=32) ----------------
__global__ void v2e1_kernel() {
    int s = blockIdx.y;
    int e = blockIdx.x * 8 + (threadIdx.x >> 5);
    int lane = threadIdx.x & 31;
    int ge = s * Ls + e;
    const int* nb = g_nbr + (size_t)ge * KN;
    int myn = (lane < KN) ? nb[lane] : 0;
    const float* h = g_h1 + (size_t)s * Ls * HID;
    float acc = 0.f;
    #pragma unroll
    for (int j = 0; j < KN; j++) {
        int v = __shfl_sync(0xffffffffu, myn, j);
        acc += h[(size_t)v * HID + lane];
    }
    g_y1[(size_t)ge * HID + lane] = acc * (1.f / KN);
}

// ---------------- kernel 8: e2v mean + relu, conv1 (warp per vertex) ----------------
__global__ void e2v1_kernel() {
    int gv = blockIdx.x * 8 + (threadIdx.x >> 5);
    int lane = threadIdx.x & 31;
    int cnt = g_dvi[gv];
    int off = g_off[gv];
    float acc = 0.f;
    for (int t = 0; t < cnt; t++) {
        int ge = g_adj[off + t];
        acc += g_y1[(size_t)ge * HID + lane];
    }
    float d = fmaxf((float)cnt, 1.f);
    g_o1[(size_t)gv * HID + lane] = fmaxf(acc / d, 0.f);
}

// ---------------- kernel 9: theta2 + BN (warp per vertex, 64 outputs) ----------------
__global__ void theta2_kernel(const float* __restrict__ w2, const float* __restrict__ b2,
                              const float* __restrict__ g2, const float* __restrict__ be2) {
    __shared__ float ws[HID * Cn];
    int tid = threadIdx.x;
    for (int t = tid; t < HID * Cn; t += 256) ws[t] = w2[t];
    __syncthreads();
    int gv = blockIdx.x * 8 + (tid >> 5);
    int lane = tid & 31;
    float f0 = g_o1[(size_t)gv * HID + lane];
    float a0 = 0.f, a1 = 0.f;
    #pragma unroll
    for (int c = 0; c < 32; c++) {
        float in = __shfl_sync(0xffffffffu, f0, c);
        a0 = fmaf(in, ws[c * Cn + lane], a0);
        a1 = fmaf(in, ws[c * Cn + lane + 32], a1);
    }
    g_h2[(size_t)gv * Cn + lane]      = (a0 + b2[lane])      * (g2[lane]      * BN_SCALE) + be2[lane];
    g_h2[(size_t)gv * Cn + lane + 32] = (a1 + b2[lane + 32]) * (g2[lane + 32] * BN_SCALE) + be2[lane + 32];
}

// ---------------- kernel 10: v2e mean, conv2 (warp per edge, F=64) ----------------
__global__ void v2e2_kernel() {
    int s = blockIdx.y;
    int e = blockIdx.x * 8 + (threadIdx.x >> 5);
    int lane = threadIdx.x & 31;
    int ge = s * Ls + e;
    const int* nb = g_nbr + (size_t)ge * KN;
    int myn = (lane < KN) ? nb[lane] : 0;
    const float* h = g_h2 + (size_t)s * Ls * Cn;
    float a0 = 0.f, a1 = 0.f;
    #pragma unroll
    for (int j = 0; j < KN; j++) {
        int v = __shfl_sync(0xffffffffu, myn, j);
        const float* hv = h + (size_t)v * Cn;
        a0 += hv[lane];
        a1 += hv[lane + 32];
    }
    g_y2[(size_t)ge * Cn + lane]      = a0 * (1.f / KN);
    g_y2[(size_t)ge * Cn + lane + 32] = a1 * (1.f / KN);
}

// ---------------- kernel 11: e2v mean, conv2 -> output ----------------
__global__ void e2v2_kernel(float* __restrict__ out) {
    int gv = blockIdx.x * 8 + (threadIdx.x >> 5);
    int lane = threadIdx.x & 31;
    int cnt = g_dvi[gv];
    int off = g_off[gv];
    float a0 = 0.f, a1 = 0.f;
    for (int t = 0; t < cnt; t++) {
        int ge = g_adj[off + t];
        const float* y = g_y2 + (size_t)ge * Cn;
        a0 += y[lane];
        a1 += y[lane + 32];
    }
    float d = fmaxf((float)cnt, 1.f);
    out[(size_t)gv * Cn + lane]      = a0 / d;
    out[(size_t)gv * Cn + lane + 32] = a1 / d;
}

// ---------------- launch ----------------
extern "C" void kernel_launch(void* const* d_in, const int* in_sizes, int n_in,
                              void* d_out, int out_size) {
    const float* x   = (const float*)d_in[0];
    const float* w1  = (const float*)d_in[1];
    const float* b1  = (const float*)d_in[2];
    const float* g1  = (const float*)d_in[3];
    const float* be1 = (const float*)d_in[4];
    const float* w2  = (const float*)d_in[5];
    const float* b2  = (const float*)d_in[6];
    const float* g2  = (const float*)d_in[7];
    const float* be2 = (const float*)d_in[8];
    float* out = (float*)d_out;

    zero_kernel<<<(NV + 255) / 256, 256>>>();
    sq_kernel<<<NV / 8, 256>>>(x);
    dist_kernel<<<dim3(Ls / 64, Ls / 64, Bn), 64>>>(x);
    topk_kernel<<<dim3(Ls, Bn), 128>>>();
    scan_kernel<<<1, 1024>>>();
    fill_kernel<<<dim3(Ls / 8, Bn), 256>>>();
    theta1_kernel<<<NV / 8, 256>>>(x, w1, b1, g1, be1);
    v2e1_kernel<<<dim3(Ls / 8, Bn), 256>>>();
    e2v1_kernel<<<NV / 8, 256>>>();
    theta2_kernel<<<NV / 8, 256>>>(w2, b2, g2, be2);
    v2e2_kernel<<<dim3(Ls / 8, Bn), 256>>>();
    e2v2_kernel<<<NV / 8, 256>>>(out);
}

// round 2
// speedup vs baseline: 1.0336x; 1.0336x over previous
#include <cuda_runtime.h>
#include <cfloat>
#include <cstdint>

#define Bn  8
#define Ls  3136      // 56*56
#define Cn  64
#define HID 32
#define KN  30
#define NV  (Bn*Ls)   // 25088 global vertices/edges

// ---------------- device scratch (static globals; no allocations) ----------------
__device__ float g_sq  [NV];
__device__ float g_d2  [(size_t)Bn*Ls*Ls];      // 314.7 MB distance matrices
__device__ int   g_nbr [(size_t)NV*KN];         // per-edge neighbor lists (sample-local idx)
__device__ int   g_dvi [NV];                    // vertex in-degree (counts)
__device__ int   g_off [NV];                    // CSR offsets (exclusive scan of g_dvi)
__device__ int   g_cnt [NV];                    // CSR fill cursors
__device__ int   g_adj [(size_t)NV*KN];         // CSR: edges incident to each vertex
__device__ float g_h1  [(size_t)NV*HID];        // conv1 theta+bn
__device__ float g_y1  [(size_t)NV*HID];        // conv1 v2e means
__device__ float g_o1  [(size_t)NV*HID];        // conv1 output (after e2v + relu)
__device__ float g_h2  [(size_t)NV*Cn];         // conv2 theta+bn
__device__ float g_y2  [(size_t)NV*Cn];         // conv2 v2e means

// 1/sqrt(1 + 1e-5) computed in double, rounded to f32 (matches reference)
#define BN_SCALE 0.99999500003749969f

// ---------------- kernel 0: zero counters ----------------
__global__ void zero_kernel() {
    int t = blockIdx.x * blockDim.x + threadIdx.x;
    if (t < NV) { g_cnt[t] = 0; g_dvi[t] = 0; }
}

// ---------------- kernel 1: row squared norms (warp per vertex) ----------------
__global__ void sq_kernel(const float* __restrict__ x) {
    int gv = blockIdx.x * 8 + (threadIdx.x >> 5);
    int lane = threadIdx.x & 31;
    const float* p = x + (size_t)gv * Cn;
    float a = p[lane] * p[lane] + p[lane + 32] * p[lane + 32];
    #pragma unroll
    for (int off = 16; off; off >>= 1) a += __shfl_down_sync(0xffffffffu, a, off);
    if (lane == 0) g_sq[gv] = a;
}

// ---------------- kernel 2: d2 = sq_i + sq_j - 2*(ft @ ft^T), symmetric tiles ----------------
// Only tiles with ti <= tj are computed; each off-diagonal block is stored twice
// (normal + register-transposed), halving the FMA work.
__global__ void __launch_bounds__(64) dist_kernel(const float* __restrict__ x) {
    int ti = blockIdx.y, tj = blockIdx.x;
    if (ti > tj) return;
    int s = blockIdx.z;
    const float* A  = x + (size_t)s * Ls * Cn;
    float*       D  = g_d2 + (size_t)s * Ls * Ls;
    const float* sq = g_sq + s * Ls;
    int i0 = ti << 6, j0 = tj << 6;

    __shared__ __align__(16) float Ast[64][68];  // [k][m]
    __shared__ __align__(16) float Bst[64][68];  // [k][n]
    int tid = threadIdx.x;   // 64 threads

    for (int f = tid; f < 1024; f += 64) {
        int m = f >> 4, kq = (f & 15) << 2;
        float4 av = *(const float4*)(A + (size_t)(i0 + m) * Cn + kq);
        Ast[kq + 0][m] = av.x; Ast[kq + 1][m] = av.y; Ast[kq + 2][m] = av.z; Ast[kq + 3][m] = av.w;
        float4 bv = *(const float4*)(A + (size_t)(j0 + m) * Cn + kq);
        Bst[kq + 0][m] = bv.x; Bst[kq + 1][m] = bv.y; Bst[kq + 2][m] = bv.z; Bst[kq + 3][m] = bv.w;
    }
    __syncthreads();

    int m0 = (tid >> 3) << 3;
    int n0 = (tid & 7) << 3;
    float acc[8][8];
    #pragma unroll
    for (int r = 0; r < 8; r++)
        #pragma unroll
        for (int c = 0; c < 8; c++) acc[r][c] = 0.f;

    #pragma unroll 8
    for (int k = 0; k < 64; k++) {
        float a[8], b[8];
        *(float4*)(a)     = *(const float4*)&Ast[k][m0];
        *(float4*)(a + 4) = *(const float4*)&Ast[k][m0 + 4];
        *(float4*)(b)     = *(const float4*)&Bst[k][n0];
        *(float4*)(b + 4) = *(const float4*)&Bst[k][n0 + 4];
        #pragma unroll
        for (int r = 0; r < 8; r++)
            #pragma unroll
            for (int c = 0; c < 8; c++) acc[r][c] = fmaf(a[r], b[c], acc[r][c]);
    }

    float sqj[8], sqi[8];
    #pragma unroll
    for (int c = 0; c < 8; c++) sqj[c] = sq[j0 + n0 + c];
    #pragma unroll
    for (int r = 0; r < 8; r++) sqi[r] = sq[i0 + m0 + r];
    #pragma unroll
    for (int r = 0; r < 8; r++)
        #pragma unroll
        for (int c = 0; c < 8; c++) acc[r][c] = sqi[r] + sqj[c] - 2.f * acc[r][c];

    // normal store
    #pragma unroll
    for (int r = 0; r < 8; r++) {
        float* drow = D + (size_t)(i0 + m0 + r) * Ls + j0 + n0;
        *(float4*)(drow)     = make_float4(acc[r][0], acc[r][1], acc[r][2], acc[r][3]);
        *(float4*)(drow + 4) = make_float4(acc[r][4], acc[r][5], acc[r][6], acc[r][7]);
    }
    // transposed store (off-diagonal tiles only)
    if (ti != tj) {
        #pragma unroll
        for (int c = 0; c < 8; c++) {
            float* drow = D + (size_t)(j0 + n0 + c) * Ls + i0 + m0;
            *(float4*)(drow)     = make_float4(acc[0][c], acc[1][c], acc[2][c], acc[3][c]);
            *(float4*)(drow + 4) = make_float4(acc[4][c], acc[5][c], acc[6][c], acc[7][c]);
        }
    }
}

// ---------------- top-K helpers ----------------
__device__ __forceinline__ void aggAdd(int* hist, int b) {
    unsigned peers = __match_any_sync(__activemask(), b);
    int lead = __ffs(peers) - 1;
    if ((int)(threadIdx.x & 31) == lead) atomicAdd(&hist[b], __popc(peers));
}

// inclusive scan across 256 threads; wsums: shared int[8]
__device__ __forceinline__ int blockScanInc(int v, int tid, int* wsums) {
    __syncthreads();                       // protect wsums reuse
    int lane = tid & 31, w = tid >> 5;
    #pragma unroll
    for (int o = 1; o < 32; o <<= 1) {
        int n = __shfl_up_sync(0xffffffffu, v, o);
        if (lane >= o) v += n;
    }
    if (lane == 31) wsums[w] = v;
    __syncthreads();
    if (w == 0) {
        int s = (lane < 8) ? wsums[lane] : 0;
        #pragma unroll
        for (int o = 1; o < 8; o <<= 1) {
            int n = __shfl_up_sync(0xffffffffu, s, o);
            if (lane >= o) s += n;
        }
        if (lane < 8) wsums[lane] = s;
    }
    __syncthreads();
    return v + ((w > 0) ? wsums[w - 1] : 0);
}

// ---------------- kernel 3: exact top-K smallest per row via 4-level radix select ----
__global__ void __launch_bounds__(256) topk_kernel() {
    int s = blockIdx.y, i = blockIdx.x;
    const float* row = g_d2 + ((size_t)s * Ls + i) * Ls;
    __shared__ unsigned su[Ls];
    __shared__ int hist[256];
    __shared__ int wsums[8];
    __shared__ int s_bucket, s_need, s_totless;
    int tid = threadIdx.x;   // 256

    hist[tid] = 0;
    __syncthreads();

    // pass 0: load + order-preserving transform + level-1 histogram (bits 31:24)
    for (int t = tid; t < Ls; t += 256) {
        unsigned u = __float_as_uint(row[t]);
        u ^= (unsigned)(((int)u >> 31)) | 0x80000000u;
        su[t] = u;
        aggAdd(hist, (int)(u >> 24));
    }
    __syncthreads();

    unsigned prefix = 0;
    int need = KN;
    #pragma unroll
    for (int lvl = 0; lvl < 4; lvl++) {
        int c = hist[tid];
        int cum = blockScanInc(c, tid, wsums);
        int cumprev = cum - c;
        if (cum >= need && cumprev < need) { s_bucket = tid; s_need = need - cumprev; }
        __syncthreads();
        prefix = (prefix << 8) | (unsigned)s_bucket;
        need = s_need;
        if (lvl == 3) break;
        hist[tid] = 0;
        __syncthreads();
        int shift = 24 - 8 * lvl;
        for (int t = tid; t < Ls; t += 256) {
            unsigned u = su[t];
            if ((u >> shift) == prefix) aggAdd(hist, (int)((u >> (shift - 8)) & 255u));
        }
        __syncthreads();
    }
    unsigned T = prefix;          // exact bits of the K-th smallest key
    int ties_needed = need;       // how many == T to take (lowest indices first)

    // emit pass: blocked ownership for stable, index-ordered, deterministic output
    int lo = tid * 13; if (lo > Ls) lo = Ls;
    int hi = lo + 13;  if (hi > Ls) hi = Ls;
    int cl = 0, ce = 0;
    for (int j = lo; j < hi; j++) {
        unsigned u = su[j];
        cl += (u < T);
        ce += (u == T);
    }
    int pack = cl | (ce << 16);
    int cumP = blockScanInc(pack, tid, wsums);
    if (tid == 255) s_totless = cumP & 0xffff;
    __syncthreads();
    int exclP = cumP - pack;
    int pl = exclP & 0xffff;
    int pe = exclP >> 16;
    int totless = s_totless;
    int* nout = g_nbr + ((size_t)s * Ls + i) * KN;
    int* dv = g_dvi + s * Ls;
    for (int j = lo; j < hi; j++) {
        unsigned u = su[j];
        if (u < T) {
            nout[pl] = j; atomicAdd(&dv[j], 1); pl++;
        } else if (u == T) {
            if (pe < ties_needed) { nout[totless + pe] = j; atomicAdd(&dv[j], 1); }
            pe++;
        }
    }
}

// ---------------- kernel 4: exclusive scan of degrees (single block) ----------------
__global__ void scan_kernel() {
    __shared__ int ps[1024];
    int tid = threadIdx.x;
    int start = tid * 25;
    int sum = 0;
    for (int t = start; t < start + 25 && t < NV; t++) sum += g_dvi[t];
    ps[tid] = sum;
    __syncthreads();
    for (int off = 1; off < 1024; off <<= 1) {
        int v = (tid >= off) ? ps[tid - off] : 0;
        __syncthreads();
        ps[tid] += v;
        __syncthreads();
    }
    int excl = (tid == 0) ? 0 : ps[tid - 1];
    for (int t = start; t < start + 25 && t < NV; t++) {
        g_off[t] = excl;
        excl += g_dvi[t];
    }
}

// ---------------- kernel 5: CSR fill (warp per edge) ----------------
__global__ void fill_kernel() {
    int s = blockIdx.y;
    int e = blockIdx.x * 8 + (threadIdx.x >> 5);
    int lane = threadIdx.x & 31;
    int ge = s * Ls + e;
    if (lane < KN) {
        int v  = g_nbr[(size_t)ge * KN + lane];
        int gv = s * Ls + v;
        int pos = atomicAdd(&g_cnt[gv], 1);
        g_adj[g_off[gv] + pos] = ge;
    }
}

// ---------------- kernel 6: theta1 + BN (warp per vertex, 32 outputs) ----------------
__global__ void theta1_kernel(const float* __restrict__ x, const float* __restrict__ w1,
                              const float* __restrict__ b1, const float* __restrict__ g1,
                              const float* __restrict__ be1) {
    __shared__ float ws[Cn * HID];
    int tid = threadIdx.x;
    for (int t = tid; t < Cn * HID; t += 256) ws[t] = w1[t];
    __syncthreads();
    int gv = blockIdx.x * 8 + (tid >> 5);
    int lane = tid & 31;
    const float* f = x + (size_t)gv * Cn;
    float f0 = f[lane], f1 = f[lane + 32];
    float acc = 0.f;
    #pragma unroll
    for (int c = 0; c < 32; c++) acc = fmaf(__shfl_sync(0xffffffffu, f0, c), ws[c * HID + lane], acc);
    #pragma unroll
    for (int c = 0; c < 32; c++) acc = fmaf(__shfl_sync(0xffffffffu, f1, c), ws[(c + 32) * HID + lane], acc);
    g_h1[(size_t)gv * HID + lane] = (acc + b1[lane]) * (g1[lane] * BN_SCALE) + be1[lane];
}

// ---------------- kernel 7: v2e mean, conv1 (warp per edge, F=32) ----------------
__global__ void v2e1_kernel() {
    int s = blockIdx.y;
    int e = blockIdx.x * 8 + (threadIdx.x >> 5);
    int lane = threadIdx.x & 31;
    int ge = s * Ls + e;
    const int* nb = g_nbr + (size_t)ge * KN;
    int myn = (lane < KN) ? nb[lane] : 0;
    const float* h = g_h1 + (size_t)s * Ls * HID;
    float acc = 0.f;
    #pragma unroll
    for (int j = 0; j < KN; j++) {
        int v = __shfl_sync(0xffffffffu, myn, j);
        acc += h[(size_t)v * HID + lane];
    }
    g_y1[(size_t)ge * HID + lane] = acc * (1.f / KN);
}

// ---------------- kernel 8: e2v mean + relu, conv1 (warp per vertex) ----------------
__global__ void e2v1_kernel() {
    int gv = blockIdx.x * 8 + (threadIdx.x >> 5);
    int lane = threadIdx.x & 31;
    int cnt = g_dvi[gv];
    int off = g_off[gv];
    float acc = 0.f;
    for (int t = 0; t < cnt; t++) {
        int ge = g_adj[off + t];
        acc += g_y1[(size_t)ge * HID + lane];
    }
    float d = fmaxf((float)cnt, 1.f);
    g_o1[(size_t)gv * HID + lane] = fmaxf(acc / d, 0.f);
}

// ---------------- kernel 9: theta2 + BN (warp per vertex, 64 outputs) ----------------
__global__ void theta2_kernel(const float* __restrict__ w2, const float* __restrict__ b2,
                              const float* __restrict__ g2, const float* __restrict__ be2) {
    __shared__ float ws[HID * Cn];
    int tid = threadIdx.x;
    for (int t = tid; t < HID * Cn; t += 256) ws[t] = w2[t];
    __syncthreads();
    int gv = blockIdx.x * 8 + (tid >> 5);
    int lane = tid & 31;
    float f0 = g_o1[(size_t)gv * HID + lane];
    float a0 = 0.f, a1 = 0.f;
    #pragma unroll
    for (int c = 0; c < 32; c++) {
        float in = __shfl_sync(0xffffffffu, f0, c);
        a0 = fmaf(in, ws[c * Cn + lane], a0);
        a1 = fmaf(in, ws[c * Cn + lane + 32], a1);
    }
    g_h2[(size_t)gv * Cn + lane]      = (a0 + b2[lane])      * (g2[lane]      * BN_SCALE) + be2[lane];
    g_h2[(size_t)gv * Cn + lane + 32] = (a1 + b2[lane + 32]) * (g2[lane + 32] * BN_SCALE) + be2[lane + 32];
}

// ---------------- kernel 10: v2e mean, conv2 (warp per edge, F=64) ----------------
__global__ void v2e2_kernel() {
    int s = blockIdx.y;
    int e = blockIdx.x * 8 + (threadIdx.x >> 5);
    int lane = threadIdx.x & 31;
    int ge = s * Ls + e;
    const int* nb = g_nbr + (size_t)ge * KN;
    int myn = (lane < KN) ? nb[lane] : 0;
    const float* h = g_h2 + (size_t)s * Ls * Cn;
    float a0 = 0.f, a1 = 0.f;
    #pragma unroll
    for (int j = 0; j < KN; j++) {
        int v = __shfl_sync(0xffffffffu, myn, j);
        const float* hv = h + (size_t)v * Cn;
        a0 += hv[lane];
        a1 += hv[lane + 32];
    }
    g_y2[(size_t)ge * Cn + lane]      = a0 * (1.f / KN);
    g_y2[(size_t)ge * Cn + lane + 32] = a1 * (1.f / KN);
}

// ---------------- kernel 11: e2v mean, conv2 -> output ----------------
__global__ void e2v2_kernel(float* __restrict__ out) {
    int gv = blockIdx.x * 8 + (threadIdx.x >> 5);
    int lane = threadIdx.x & 31;
    int cnt = g_dvi[gv];
    int off = g_off[gv];
    float a0 = 0.f, a1 = 0.f;
    for (int t = 0; t < cnt; t++) {
        int ge = g_adj[off + t];
        const float* y = g_y2 + (size_t)ge * Cn;
        a0 += y[lane];
        a1 += y[lane + 32];
    }
    float d = fmaxf((float)cnt, 1.f);
    out[(size_t)gv * Cn + lane]      = a0 / d;
    out[(size_t)gv * Cn + lane + 32] = a1 / d;
}

// ---------------- launch ----------------
extern "C" void kernel_launch(void* const* d_in, const int* in_sizes, int n_in,
                              void* d_out, int out_size) {
    const float* x   = (const float*)d_in[0];
    const float* w1  = (const float*)d_in[1];
    const float* b1  = (const float*)d_in[2];
    const float* g1  = (const float*)d_in[3];
    const float* be1 = (const float*)d_in[4];
    const float* w2  = (const float*)d_in[5];
    const float* b2  = (const float*)d_in[6];
    const float* g2  = (const float*)d_in[7];
    const float* be2 = (const float*)d_in[8];
    float* out = (float*)d_out;

    zero_kernel<<<(NV + 255) / 256, 256>>>();
    sq_kernel<<<NV / 8, 256>>>(x);
    dist_kernel<<<dim3(Ls / 64, Ls / 64, Bn), 64>>>(x);
    topk_kernel<<<dim3(Ls, Bn), 256>>>();
    scan_kernel<<<1, 1024>>>();
    fill_kernel<<<dim3(Ls / 8, Bn), 256>>>();
    theta1_kernel<<<NV / 8, 256>>>(x, w1, b1, g1, be1);
    v2e1_kernel<<<dim3(Ls / 8, Bn), 256>>>();
    e2v1_kernel<<<NV / 8, 256>>>();
    theta2_kernel<<<NV / 8, 256>>>(w2, b2, g2, be2);
    v2e2_kernel<<<dim3(Ls / 8, Bn), 256>>>();
    e2v2_kernel<<<NV / 8, 256>>>(out);
}

// round 3
// speedup vs baseline: 1.3652x; 1.3208x over previous
#include <cuda_runtime.h>
#include <cfloat>
#include <cstdint>

#define Bn  8
#define Ls  3136      // 56*56
#define Cn  64
#define HID 32
#define KN  30
#define NV  (Bn*Ls)   // 25088 global vertices/edges

// ---------------- device scratch (static globals; no allocations) ----------------
__device__ float g_sq  [NV];
__device__ float g_d2  [(size_t)Bn*Ls*Ls];      // 314.7 MB distance matrices
__device__ int   g_nbr [(size_t)NV*KN];         // per-edge neighbor lists (sample-local idx)
__device__ int   g_dvi [NV];                    // vertex in-degree (counts)
__device__ int   g_off [NV];                    // CSR offsets (exclusive scan of g_dvi)
__device__ int   g_cnt [NV];                    // CSR fill cursors
__device__ int   g_adj [(size_t)NV*KN];         // CSR: edges incident to each vertex
__device__ float g_h1  [(size_t)NV*HID];        // conv1 theta+bn
__device__ float g_y1  [(size_t)NV*HID];        // conv1 v2e means
__device__ float g_o1  [(size_t)NV*HID];        // conv1 output (after e2v + relu)
__device__ float g_h2  [(size_t)NV*Cn];         // conv2 theta+bn
__device__ float g_y2  [(size_t)NV*Cn];         // conv2 v2e means

// 1/sqrt(1 + 1e-5) computed in double, rounded to f32 (matches reference)
#define BN_SCALE 0.99999500003749969f

// order-preserving float->uint transform
#define FLIPU(u) ((u) ^ ((unsigned)(((int)(u)) >> 31) | 0x80000000u))

// ---------------- kernel 0: zero counters ----------------
__global__ void zero_kernel() {
    int t = blockIdx.x * blockDim.x + threadIdx.x;
    if (t < NV) { g_cnt[t] = 0; g_dvi[t] = 0; }
}

// ---------------- kernel 1: row squared norms (warp per vertex) ----------------
__global__ void sq_kernel(const float* __restrict__ x) {
    int gv = blockIdx.x * 8 + (threadIdx.x >> 5);
    int lane = threadIdx.x & 31;
    const float* p = x + (size_t)gv * Cn;
    float a = p[lane] * p[lane] + p[lane + 32] * p[lane + 32];
    #pragma unroll
    for (int off = 16; off; off >>= 1) a += __shfl_down_sync(0xffffffffu, a, off);
    if (lane == 0) g_sq[gv] = a;
}

// ---------------- kernel 2: d2 = sq_i + sq_j - 2*(ft @ ft^T), symmetric tiles ----------------
__global__ void __launch_bounds__(64) dist_kernel(const float* __restrict__ x) {
    int ti = blockIdx.y, tj = blockIdx.x;
    if (ti > tj) return;
    int s = blockIdx.z;
    const float* A  = x + (size_t)s * Ls * Cn;
    float*       D  = g_d2 + (size_t)s * Ls * Ls;
    const float* sq = g_sq + s * Ls;
    int i0 = ti << 6, j0 = tj << 6;

    __shared__ __align__(16) float Ast[64][68];
    __shared__ __align__(16) float Bst[64][68];
    int tid = threadIdx.x;   // 64 threads

    for (int f = tid; f < 1024; f += 64) {
        int m = f >> 4, kq = (f & 15) << 2;
        float4 av = *(const float4*)(A + (size_t)(i0 + m) * Cn + kq);
        Ast[kq + 0][m] = av.x; Ast[kq + 1][m] = av.y; Ast[kq + 2][m] = av.z; Ast[kq + 3][m] = av.w;
        float4 bv = *(const float4*)(A + (size_t)(j0 + m) * Cn + kq);
        Bst[kq + 0][m] = bv.x; Bst[kq + 1][m] = bv.y; Bst[kq + 2][m] = bv.z; Bst[kq + 3][m] = bv.w;
    }
    __syncthreads();

    int m0 = (tid >> 3) << 3;
    int n0 = (tid & 7) << 3;
    float acc[8][8];
    #pragma unroll
    for (int r = 0; r < 8; r++)
        #pragma unroll
        for (int c = 0; c < 8; c++) acc[r][c] = 0.f;

    #pragma unroll 8
    for (int k = 0; k < 64; k++) {
        float a[8], b[8];
        *(float4*)(a)     = *(const float4*)&Ast[k][m0];
        *(float4*)(a + 4) = *(const float4*)&Ast[k][m0 + 4];
        *(float4*)(b)     = *(const float4*)&Bst[k][n0];
        *(float4*)(b + 4) = *(const float4*)&Bst[k][n0 + 4];
        #pragma unroll
        for (int r = 0; r < 8; r++)
            #pragma unroll
            for (int c = 0; c < 8; c++) acc[r][c] = fmaf(a[r], b[c], acc[r][c]);
    }

    float sqj[8], sqi[8];
    #pragma unroll
    for (int c = 0; c < 8; c++) sqj[c] = sq[j0 + n0 + c];
    #pragma unroll
    for (int r = 0; r < 8; r++) sqi[r] = sq[i0 + m0 + r];
    #pragma unroll
    for (int r = 0; r < 8; r++)
        #pragma unroll
        for (int c = 0; c < 8; c++) acc[r][c] = sqi[r] + sqj[c] - 2.f * acc[r][c];

    #pragma unroll
    for (int r = 0; r < 8; r++) {
        float* drow = D + (size_t)(i0 + m0 + r) * Ls + j0 + n0;
        *(float4*)(drow)     = make_float4(acc[r][0], acc[r][1], acc[r][2], acc[r][3]);
        *(float4*)(drow + 4) = make_float4(acc[r][4], acc[r][5], acc[r][6], acc[r][7]);
    }
    if (ti != tj) {
        #pragma unroll
        for (int c = 0; c < 8; c++) {
            float* drow = D + (size_t)(j0 + n0 + c) * Ls + i0 + m0;
            *(float4*)(drow)     = make_float4(acc[0][c], acc[1][c], acc[2][c], acc[3][c]);
            *(float4*)(drow + 4) = make_float4(acc[4][c], acc[5][c], acc[6][c], acc[7][c]);
        }
    }
}

// inclusive scan across 256 threads; wsums: shared int[8]
__device__ __forceinline__ int blockScanInc(int v, int tid, int* wsums) {
    __syncthreads();
    int lane = tid & 31, w = tid >> 5;
    #pragma unroll
    for (int o = 1; o < 32; o <<= 1) {
        int n = __shfl_up_sync(0xffffffffu, v, o);
        if (lane >= o) v += n;
    }
    if (lane == 31) wsums[w] = v;
    __syncthreads();
    if (w == 0) {
        int s = (lane < 8) ? wsums[lane] : 0;
        #pragma unroll
        for (int o = 1; o < 8; o <<= 1) {
            int n = __shfl_up_sync(0xffffffffu, s, o);
            if (lane >= o) s += n;
        }
        if (lane < 8) wsums[lane] = s;
    }
    __syncthreads();
    return v + ((w > 0) ? wsums[w - 1] : 0);
}

// ---------------- kernel 3: exact top-K via 12-bit histogram + candidate rank ----------
#define HCAP 1024   // candidate capacity (overlaid on hist)
__global__ void __launch_bounds__(256) topk_kernel() {
    int s = blockIdx.y, i = blockIdx.x;
    const uint4* row4 = (const uint4*)(g_d2 + ((size_t)s * Ls + i) * Ls);
    __shared__ __align__(16) unsigned su[Ls];
    __shared__ __align__(16) int hist[4096];
    __shared__ int wsums[8];
    __shared__ int s_B, s_need, s_cless, s_ce;
    __shared__ int s_selctr, s_cctr, s_base;
    int tid = threadIdx.x;   // 256

    // zero hist (each thread owns 16 contiguous entries)
    #pragma unroll
    for (int r = 0; r < 16; r += 4)
        *(int4*)&hist[tid * 16 + r] = make_int4(0, 0, 0, 0);
    if (tid == 0) { s_selctr = 0; s_cctr = 0; s_base = 0; }
    __syncthreads();

    // load pass: 784 uint4 = 3136 keys; high-MLP vector loads
    uint4 v0 = row4[tid];
    uint4 v1 = row4[tid + 256];
    uint4 v2 = row4[tid + 512];
    uint4 v3 = make_uint4(0, 0, 0, 0);
    bool rem = (tid < 784 - 768);
    if (rem) v3 = row4[tid + 768];

    #define PROC(vv, tt) {                                             \
        unsigned a = FLIPU(vv.x), b = FLIPU(vv.y),                     \
                 c = FLIPU(vv.z), d = FLIPU(vv.w);                     \
        *(uint4*)&su[(tt) * 4] = make_uint4(a, b, c, d);               \
        atomicAdd(&hist[a >> 20], 1); atomicAdd(&hist[b >> 20], 1);    \
        atomicAdd(&hist[c >> 20], 1); atomicAdd(&hist[d >> 20], 1);    \
    }
    PROC(v0, tid);
    PROC(v1, tid + 256);
    PROC(v2, tid + 512);
    if (rem) PROC(v3, tid + 768);
    #undef PROC
    __syncthreads();

    // find bucket containing the 30th smallest
    int csum = 0;
    #pragma unroll
    for (int r = 0; r < 16; r++) csum += hist[tid * 16 + r];
    int cum = blockScanInc(csum, tid, wsums);
    if (cum >= KN && cum - csum < KN) {
        int run = cum - csum;
        #pragma unroll
        for (int r = 0; r < 16; r++) {
            int h = hist[tid * 16 + r];
            if (run + h >= KN) { s_B = tid * 16 + r; s_cless = run; s_need = KN - run; s_ce = h; break; }
            run += h;
        }
    }
    __syncthreads();

    unsigned prefix = (unsigned)s_B;
    int shift = 20;
    int cless = s_cless, need = s_need, ce = s_ce;

    // rare fallback: refine prefix until candidate bucket fits (or key exact)
    while (ce > HCAP && shift > 0) {
        int nb_bits = (shift == 20) ? 12 : 8;
        int nshift = shift - nb_bits;
        for (int r = tid; r < (1 << nb_bits); r += 256) hist[r] = 0;
        __syncthreads();
        for (int t = tid; t < Ls; t += 256) {
            unsigned u = su[t];
            if ((u >> shift) == prefix)
                atomicAdd(&hist[(u >> nshift) & ((1u << nb_bits) - 1u)], 1);
        }
        __syncthreads();
        if (tid == 0) {
            int run = cless;
            for (int r = 0; r < (1 << nb_bits); r++) {
                int h = hist[r];
                if (run + h >= KN) { s_B = r; s_cless = run; s_need = KN - run; s_ce = h; break; }
                run += h;
            }
        }
        __syncthreads();
        prefix = (prefix << nb_bits) | (unsigned)s_B;
        shift = nshift;
        cless = s_cless; need = s_need; ce = s_ce;
    }

    int* nout = g_nbr + ((size_t)s * Ls + i) * KN;
    int* dv = g_dvi + s * Ls;

    // candidates overlay the (no longer needed) histogram
    unsigned* cand_k = (unsigned*)hist;
    int*      cand_i = hist + HCAP;

    // emit pass: sure-selected directly; boundary bucket -> candidates
    for (int t = tid; t < Ls; t += 256) {
        unsigned u = su[t];
        unsigned hi = u >> shift;
        if (hi < prefix) {
            int p = atomicAdd(&s_selctr, 1);
            nout[p] = t;
            atomicAdd(&dv[t], 1);
        } else if (hi == prefix) {
            int p = atomicAdd(&s_cctr, 1);
            if (p < HCAP) { cand_k[p] = u; cand_i[p] = t; }
        }
    }
    __syncthreads();

    if (ce <= HCAP) {
        // exact rank among candidates by (key, idx)
        int totc = s_cctr;
        for (int cdx = tid; cdx < totc; cdx += 256) {
            unsigned k = cand_k[cdx];
            int idx = cand_i[cdx];
            int rank = 0;
            for (int j = 0; j < totc; j++) {
                unsigned kj = cand_k[j];
                rank += (kj < k) || (kj == k && cand_i[j] < idx);
            }
            if (rank < need) {
                nout[cless + rank] = idx;
                atomicAdd(&dv[idx], 1);
            }
        }
    } else {
        // degenerate: exact key == prefix (shift==0); take lowest indices
        for (int t0 = 0; t0 < Ls; t0 += 256) {
            int t = t0 + tid;
            int m = (t < Ls) && (su[t] == prefix);
            int pos = blockScanInc(m, tid, wsums);
            int base = s_base;
            __syncthreads();
            if (tid == 255) s_base = base + pos;
            if (m) {
                int r = base + pos - 1;
                if (r < need) { nout[cless + r] = t; atomicAdd(&dv[t], 1); }
            }
        }
    }
}

// ---------------- kernel 4: exclusive scan of degrees (single block) ----------------
__global__ void scan_kernel() {
    __shared__ int ps[1024];
    int tid = threadIdx.x;
    int start = tid * 25;
    int sum = 0;
    for (int t = start; t < start + 25 && t < NV; t++) sum += g_dvi[t];
    ps[tid] = sum;
    __syncthreads();
    for (int off = 1; off < 1024; off <<= 1) {
        int v = (tid >= off) ? ps[tid - off] : 0;
        __syncthreads();
        ps[tid] += v;
        __syncthreads();
    }
    int excl = (tid == 0) ? 0 : ps[tid - 1];
    for (int t = start; t < start + 25 && t < NV; t++) {
        g_off[t] = excl;
        excl += g_dvi[t];
    }
}

// ---------------- kernel 5: CSR fill (warp per edge) ----------------
__global__ void fill_kernel() {
    int s = blockIdx.y;
    int e = blockIdx.x * 8 + (threadIdx.x >> 5);
    int lane = threadIdx.x & 31;
    int ge = s * Ls + e;
    if (lane < KN) {
        int v  = g_nbr[(size_t)ge * KN + lane];
        int gv = s * Ls + v;
        int pos = atomicAdd(&g_cnt[gv], 1);
        g_adj[g_off[gv] + pos] = ge;
    }
}

// ---------------- kernel 6: theta1 + BN (warp per vertex, 32 outputs) ----------------
__global__ void theta1_kernel(const float* __restrict__ x, const float* __restrict__ w1,
                              const float* __restrict__ b1, const float* __restrict__ g1,
                              const float* __restrict__ be1) {
    __shared__ float ws[Cn * HID];
    int tid = threadIdx.x;
    for (int t = tid; t < Cn * HID; t += 256) ws[t] = w1[t];
    __syncthreads();
    int gv = blockIdx.x * 8 + (tid >> 5);
    int lane = tid & 31;
    const float* f = x + (size_t)gv * Cn;
    float f0 = f[lane], f1 = f[lane + 32];
    float acc = 0.f;
    #pragma unroll
    for (int c = 0; c < 32; c++) acc = fmaf(__shfl_sync(0xffffffffu, f0, c), ws[c * HID + lane], acc);
    #pragma unroll
    for (int c = 0; c < 32; c++) acc = fmaf(__shfl_sync(0xffffffffu, f1, c), ws[(c + 32) * HID + lane], acc);
    g_h1[(size_t)gv * HID + lane] = (acc + b1[lane]) * (g1[lane] * BN_SCALE) + be1[lane];
}

// ---------------- kernel 7: v2e mean, conv1 (warp per edge, F=32) ----------------
__global__ void v2e1_kernel() {
    int s = blockIdx.y;
    int e = blockIdx.x * 8 + (threadIdx.x >> 5);
    int lane = threadIdx.x & 31;
    int ge = s * Ls + e;
    const int* nb = g_nbr + (size_t)ge * KN;
    int myn = (lane < KN) ? nb[lane] : 0;
    const float* h = g_h1 + (size_t)s * Ls * HID;
    float acc = 0.f;
    #pragma unroll
    for (int j = 0; j < KN; j++) {
        int v = __shfl_sync(0xffffffffu, myn, j);
        acc += h[(size_t)v * HID + lane];
    }
    g_y1[(size_t)ge * HID + lane] = acc * (1.f / KN);
}

// ---------------- kernel 8: e2v mean + relu, conv1 (warp per vertex) ----------------
__global__ void e2v1_kernel() {
    int gv = blockIdx.x * 8 + (threadIdx.x >> 5);
    int lane = threadIdx.x & 31;
    int cnt = g_dvi[gv];
    int off = g_off[gv];
    float acc = 0.f;
    for (int t = 0; t < cnt; t++) {
        int ge = g_adj[off + t];
        acc += g_y1[(size_t)ge * HID + lane];
    }
    float d = fmaxf((float)cnt, 1.f);
    g_o1[(size_t)gv * HID + lane] = fmaxf(acc / d, 0.f);
}

// ---------------- kernel 9: theta2 + BN (warp per vertex, 64 outputs) ----------------
__global__ void theta2_kernel(const float* __restrict__ w2, const float* __restrict__ b2,
                              const float* __restrict__ g2, const float* __restrict__ be2) {
    __shared__ float ws[HID * Cn];
    int tid = threadIdx.x;
    for (int t = tid; t < HID * Cn; t += 256) ws[t] = w2[t];
    __syncthreads();
    int gv = blockIdx.x * 8 + (tid >> 5);
    int lane = tid & 31;
    float f0 = g_o1[(size_t)gv * HID + lane];
    float a0 = 0.f, a1 = 0.f;
    #pragma unroll
    for (int c = 0; c < 32; c++) {
        float in = __shfl_sync(0xffffffffu, f0, c);
        a0 = fmaf(in, ws[c * Cn + lane], a0);
        a1 = fmaf(in, ws[c * Cn + lane + 32], a1);
    }
    g_h2[(size_t)gv * Cn + lane]      = (a0 + b2[lane])      * (g2[lane]      * BN_SCALE) + be2[lane];
    g_h2[(size_t)gv * Cn + lane + 32] = (a1 + b2[lane + 32]) * (g2[lane + 32] * BN_SCALE) + be2[lane + 32];
}

// ---------------- kernel 10: v2e mean, conv2 (warp per edge, F=64) ----------------
__global__ void v2e2_kernel() {
    int s = blockIdx.y;
    int e = blockIdx.x * 8 + (threadIdx.x >> 5);
    int lane = threadIdx.x & 31;
    int ge = s * Ls + e;
    const int* nb = g_nbr + (size_t)ge * KN;
    int myn = (lane < KN) ? nb[lane] : 0;
    const float* h = g_h2 + (size_t)s * Ls * Cn;
    float a0 = 0.f, a1 = 0.f;
    #pragma unroll
    for (int j = 0; j < KN; j++) {
        int v = __shfl_sync(0xffffffffu, myn, j);
        const float* hv = h + (size_t)v * Cn;
        a0 += hv[lane];
        a1 += hv[lane + 32];
    }
    g_y2[(size_t)ge * Cn + lane]      = a0 * (1.f / KN);
    g_y2[(size_t)ge * Cn + lane + 32] = a1 * (1.f / KN);
}

// ---------------- kernel 11: e2v mean, conv2 -> output ----------------
__global__ void e2v2_kernel(float* __restrict__ out) {
    int gv = blockIdx.x * 8 + (threadIdx.x >> 5);
    int lane = threadIdx.x & 31;
    int cnt = g_dvi[gv];
    int off = g_off[gv];
    float a0 = 0.f, a1 = 0.f;
    for (int t = 0; t < cnt; t++) {
        int ge = g_adj[off + t];
        const float* y = g_y2 + (size_t)ge * Cn;
        a0 += y[lane];
        a1 += y[lane + 32];
    }
    float d = fmaxf((float)cnt, 1.f);
    out[(size_t)gv * Cn + lane]      = a0 / d;
    out[(size_t)gv * Cn + lane + 32] = a1 / d;
}

// ---------------- launch ----------------
extern "C" void kernel_launch(void* const* d_in, const int* in_sizes, int n_in,
                              void* d_out, int out_size) {
    const float* x   = (const float*)d_in[0];
    const float* w1  = (const float*)d_in[1];
    const float* b1  = (const float*)d_in[2];
    const float* g1  = (const float*)d_in[3];
    const float* be1 = (const float*)d_in[4];
    const float* w2  = (const float*)d_in[5];
    const float* b2  = (const float*)d_in[6];
    const float* g2  = (const float*)d_in[7];
    const float* be2 = (const float*)d_in[8];
    float* out = (float*)d_out;

    zero_kernel<<<(NV + 255) / 256, 256>>>();
    sq_kernel<<<NV / 8, 256>>>(x);
    dist_kernel<<<dim3(Ls / 64, Ls / 64, Bn), 64>>>(x);
    topk_kernel<<<dim3(Ls, Bn), 256>>>();
    scan_kernel<<<1, 1024>>>();
    fill_kernel<<<dim3(Ls / 8, Bn), 256>>>();
    theta1_kernel<<<NV / 8, 256>>>(x, w1, b1, g1, be1);
    v2e1_kernel<<<dim3(Ls / 8, Bn), 256>>>();
    e2v1_kernel<<<NV / 8, 256>>>();
    theta2_kernel<<<NV / 8, 256>>>(w2, b2, g2, be2);
    v2e2_kernel<<<dim3(Ls / 8, Bn), 256>>>();
    e2v2_kernel<<<NV / 8, 256>>>(out);
}